// round 1
// baseline (speedup 1.0000x reference)
#include <cuda_runtime.h>

// Problem constants
#define BB 2
#define SS 2048
#define DD 1024
#define HH 16
#define HD 64
#define NTOK (BB*SS)   // 4096

// Scratch (64 MB total) — __device__ globals per allocation rules.
__device__ float g_q[BB*SS*DD];
__device__ float g_k[BB*SS*DD];
__device__ float g_v[BB*SS*DD];
__device__ float g_o[BB*SS*DD];

// ---------------------------------------------------------------------------
// SGEMM body: Y[m,n] = sum_k X[m,k] * W[n,k] + bias[n]
// X: [M,1024] row-major, W: [1024,1024] row-major ([out,in] torch layout).
// Tile 128x128x16, 256 threads, 8x8 per-thread microtile.
// ---------------------------------------------------------------------------
__device__ __forceinline__ void gemm_body(
    const float* __restrict__ X, const float* __restrict__ W,
    const float* __restrict__ bias, float* __restrict__ Y)
{
    __shared__ float As[16][132];   // [k][m], padded to kill store conflicts
    __shared__ float Bs[16][132];   // [k][n]

    const int tid = threadIdx.x;
    const int bm  = blockIdx.y * 128;
    const int bn  = blockIdx.x * 128;
    const int ty  = tid >> 4;      // 0..15
    const int tx  = tid & 15;      // 0..15

    float acc[8][8];
#pragma unroll
    for (int i = 0; i < 8; i++)
#pragma unroll
        for (int j = 0; j < 8; j++) acc[i][j] = 0.f;

    for (int kt = 0; kt < DD; kt += 16) {
        // Load A tile [128x16] and B tile [128x16], stored transposed [k][mn].
#pragma unroll
        for (int l = 0; l < 2; l++) {
            int li  = tid + l * 256;        // 0..511
            int row = li >> 2;              // 0..127
            int k4  = (li & 3) << 2;        // 0,4,8,12
            float4 av = *(const float4*)(X + (size_t)(bm + row) * DD + kt + k4);
            As[k4+0][row] = av.x; As[k4+1][row] = av.y;
            As[k4+2][row] = av.z; As[k4+3][row] = av.w;
            float4 bv = *(const float4*)(W + (size_t)(bn + row) * DD + kt + k4);
            Bs[k4+0][row] = bv.x; Bs[k4+1][row] = bv.y;
            Bs[k4+2][row] = bv.z; Bs[k4+3][row] = bv.w;
        }
        __syncthreads();

#pragma unroll
        for (int k = 0; k < 16; k++) {
            float a[8], b[8];
            *(float4*)&a[0] = *(const float4*)&As[k][ty*8];
            *(float4*)&a[4] = *(const float4*)&As[k][ty*8 + 4];
            *(float4*)&b[0] = *(const float4*)&Bs[k][tx*8];
            *(float4*)&b[4] = *(const float4*)&Bs[k][tx*8 + 4];
#pragma unroll
            for (int i = 0; i < 8; i++)
#pragma unroll
                for (int j = 0; j < 8; j++)
                    acc[i][j] += a[i] * b[j];
        }
        __syncthreads();
    }

    // Epilogue: bias + store
#pragma unroll
    for (int i = 0; i < 8; i++) {
        int m = bm + ty*8 + i;
#pragma unroll
        for (int j = 0; j < 8; j += 4) {
            int n = bn + tx*8 + j;
            float4 r;
            r.x = acc[i][j+0] + bias[n+0];
            r.y = acc[i][j+1] + bias[n+1];
            r.z = acc[i][j+2] + bias[n+2];
            r.w = acc[i][j+3] + bias[n+3];
            *(float4*)(Y + (size_t)m * DD + n) = r;
        }
    }
}

// Fused Q/K/V projection: gridDim.z = 3 selects weight/bias/output.
__global__ __launch_bounds__(256, 2) void qkv_kernel(
    const float* __restrict__ X,
    const float* __restrict__ qw, const float* __restrict__ qb,
    const float* __restrict__ kw, const float* __restrict__ kb,
    const float* __restrict__ vw, const float* __restrict__ vb)
{
    const float* W = qw; const float* bias = qb; float* Y = g_q;
    if (blockIdx.z == 1) { W = kw; bias = kb; Y = g_k; }
    if (blockIdx.z == 2) { W = vw; bias = vb; Y = g_v; }
    gemm_body(X, W, bias, Y);
}

__global__ __launch_bounds__(256, 2) void oproj_kernel(
    const float* __restrict__ ow, const float* __restrict__ ob,
    float* __restrict__ out)
{
    gemm_body(g_o, ow, ob, out);
}

// ---------------------------------------------------------------------------
// Per-head LayerNorm over Q and K, in place. One warp per 64-elem row.
// Rows: 2 tensors * (B*S*H) = 131072. 8 warps/block -> 16384 blocks.
// ---------------------------------------------------------------------------
__global__ __launch_bounds__(256) void ln_kernel(
    const float* __restrict__ qg, const float* __restrict__ qb,
    const float* __restrict__ kg, const float* __restrict__ kb)
{
    const int warp = threadIdx.x >> 5;
    const int lane = threadIdx.x & 31;
    int row = blockIdx.x * 8 + warp;             // 0 .. 131071
    const int NR = BB*SS*HH;                     // 65536

    float* buf; const float* g; const float* b;
    if (row < NR) { buf = g_q; g = qg; b = qb; }
    else          { buf = g_k; g = kg; b = kb; row -= NR; }

    float* p = buf + (size_t)row * HD;
    float x0 = p[lane], x1 = p[lane + 32];

    float s = x0 + x1;
#pragma unroll
    for (int off = 16; off; off >>= 1) s += __shfl_xor_sync(~0u, s, off);
    float mu = s * (1.f / 64.f);

    float d0 = x0 - mu, d1 = x1 - mu;
    float vv = d0*d0 + d1*d1;
#pragma unroll
    for (int off = 16; off; off >>= 1) vv += __shfl_xor_sync(~0u, vv, off);
    float rstd = rsqrtf(vv * (1.f / 64.f) + 1e-5f);

    p[lane]      = d0 * rstd * g[lane]      + b[lane];
    p[lane + 32] = d1 * rstd * g[lane + 32] + b[lane + 32];
}

// ---------------------------------------------------------------------------
// Flash attention, fp32. One block = 64 queries of one (b,h).
// Smem: Qs (transposed, scale prefolded) + Ks (transposed, XOR-swizzled,
// later reused as P) + Vs (natural) = exactly 48 KB static.
// Thread (ty,tx): rows ty*4..+3, cols/dims tx*4..+3. Row group = half-warp,
// so softmax reductions are width-16 shfls.
// ---------------------------------------------------------------------------
__global__ __launch_bounds__(256) void flash_kernel()
{
    __shared__ float Qs[64*64];   // [d][r]
    __shared__ float Ks[64*64];   // [k][c] swizzled; reused as P [r][c]
    __shared__ float Vs[64*64];   // [c][d]

    const int tid = threadIdx.x;
    const int ty = tid >> 4, tx = tid & 15;
    const int b = blockIdx.z, h = blockIdx.y;
    const int q0 = blockIdx.x * 64;
    const size_t base = (size_t)b * SS * DD + (size_t)h * HD;
    const float* Qg = g_q + base;
    const float* Kg = g_k + base;
    const float* Vg = g_v + base;

    // Load Q tile transposed, folding in softmax scale 1/sqrt(64).
#pragma unroll
    for (int l = 0; l < 4; l++) {
        int idx = tid + l * 256;
        int r   = idx >> 4;
        int d0  = (idx & 15) << 2;
        float4 v = *(const float4*)(Qg + (size_t)(q0 + r) * DD + d0);
        Qs[(d0+0)*64 + r] = v.x * 0.125f;
        Qs[(d0+1)*64 + r] = v.y * 0.125f;
        Qs[(d0+2)*64 + r] = v.z * 0.125f;
        Qs[(d0+3)*64 + r] = v.w * 0.125f;
    }

    float m[4], l[4], o[4][4];
#pragma unroll
    for (int i = 0; i < 4; i++) {
        m[i] = -1e30f; l[i] = 0.f;
#pragma unroll
        for (int j = 0; j < 4; j++) o[i][j] = 0.f;
    }

    for (int c0 = 0; c0 < SS; c0 += 64) {
        __syncthreads();  // previous iter done reading Ks(P)/Vs; also covers Qs fill

        // Load K tile transposed + XOR-swizzled, V tile natural.
#pragma unroll
        for (int lq = 0; lq < 4; lq++) {
            int idx = tid + lq * 256;
            int r   = idx >> 4;              // kv token within tile
            int d0  = (idx & 15) << 2;
            float4 kv = *(const float4*)(Kg + (size_t)(c0 + r) * DD + d0);
            int cg = r >> 2, cl = r & 3;
            Ks[(d0+0)*64 + (((cg ^ ((d0+0) & 15)) << 2) | cl)] = kv.x;
            Ks[(d0+1)*64 + (((cg ^ ((d0+1) & 15)) << 2) | cl)] = kv.y;
            Ks[(d0+2)*64 + (((cg ^ ((d0+2) & 15)) << 2) | cl)] = kv.z;
            Ks[(d0+3)*64 + (((cg ^ ((d0+3) & 15)) << 2) | cl)] = kv.w;
            float4 vv = *(const float4*)(Vg + (size_t)(c0 + r) * DD + d0);
            *(float4*)&Vs[r*64 + d0] = vv;
        }
        __syncthreads();

        // S = (Q*scale) @ K^T  — 4x4 per thread
        float s[4][4];
#pragma unroll
        for (int i = 0; i < 4; i++)
#pragma unroll
            for (int j = 0; j < 4; j++) s[i][j] = 0.f;

#pragma unroll
        for (int k = 0; k < 64; k++) {
            float a[4], bb[4];
            *(float4*)a  = *(const float4*)&Qs[k*64 + (ty << 2)];
            *(float4*)bb = *(const float4*)&Ks[k*64 + ((tx ^ (k & 15)) << 2)];
#pragma unroll
            for (int i = 0; i < 4; i++)
#pragma unroll
                for (int j = 0; j < 4; j++)
                    s[i][j] += a[i] * bb[j];
        }
        __syncthreads();   // all threads done reading Ks -> safe to overwrite with P

        // Online softmax + write P into Ks region.
#pragma unroll
        for (int i = 0; i < 4; i++) {
            float sm = fmaxf(fmaxf(s[i][0], s[i][1]), fmaxf(s[i][2], s[i][3]));
            sm = fmaxf(sm, __shfl_xor_sync(~0u, sm, 1, 16));
            sm = fmaxf(sm, __shfl_xor_sync(~0u, sm, 2, 16));
            sm = fmaxf(sm, __shfl_xor_sync(~0u, sm, 4, 16));
            sm = fmaxf(sm, __shfl_xor_sync(~0u, sm, 8, 16));
            float mnew = fmaxf(m[i], sm);
            float corr = __expf(m[i] - mnew);
            m[i] = mnew;
            float p0 = __expf(s[i][0] - mnew);
            float p1 = __expf(s[i][1] - mnew);
            float p2 = __expf(s[i][2] - mnew);
            float p3 = __expf(s[i][3] - mnew);
            float ps = p0 + p1 + p2 + p3;
            ps += __shfl_xor_sync(~0u, ps, 1, 16);
            ps += __shfl_xor_sync(~0u, ps, 2, 16);
            ps += __shfl_xor_sync(~0u, ps, 4, 16);
            ps += __shfl_xor_sync(~0u, ps, 8, 16);
            l[i] = l[i] * corr + ps;
#pragma unroll
            for (int j = 0; j < 4; j++) o[i][j] *= corr;
            float4 pv; pv.x = p0; pv.y = p1; pv.z = p2; pv.w = p3;
            *(float4*)&Ks[((ty << 2) + i)*64 + (tx << 2)] = pv;
        }
        __syncthreads();

        // O += P @ V   (c unrolled by 4 so P reads are float4)
#pragma unroll
        for (int c = 0; c < 64; c += 4) {
            float pr[4][4];
#pragma unroll
            for (int i = 0; i < 4; i++)
                *(float4*)pr[i] = *(const float4*)&Ks[((ty << 2) + i)*64 + c];
#pragma unroll
            for (int cc = 0; cc < 4; cc++) {
                float v[4];
                *(float4*)v = *(const float4*)&Vs[(c + cc)*64 + (tx << 2)];
#pragma unroll
                for (int i = 0; i < 4; i++)
#pragma unroll
                    for (int j = 0; j < 4; j++)
                        o[i][j] += pr[i][cc] * v[j];
            }
        }
    }

    // Normalize and store to g_o in [B,S,H,HD] layout.
    float* Og = g_o + base;
#pragma unroll
    for (int i = 0; i < 4; i++) {
        float inv = 1.f / l[i];
        float4 r;
        r.x = o[i][0]*inv; r.y = o[i][1]*inv;
        r.z = o[i][2]*inv; r.w = o[i][3]*inv;
        *(float4*)(Og + (size_t)(q0 + (ty << 2) + i) * DD + (tx << 2)) = r;
    }
}

// ---------------------------------------------------------------------------
extern "C" void kernel_launch(void* const* d_in, const int* in_sizes, int n_in,
                              void* d_out, int out_size)
{
    const float* x   = (const float*)d_in[0];
    const float* qw  = (const float*)d_in[1];
    const float* qb  = (const float*)d_in[2];
    const float* kw  = (const float*)d_in[3];
    const float* kb  = (const float*)d_in[4];
    const float* vw  = (const float*)d_in[5];
    const float* vb  = (const float*)d_in[6];
    const float* ow  = (const float*)d_in[7];
    const float* ob  = (const float*)d_in[8];
    const float* qlg = (const float*)d_in[9];
    const float* qlb = (const float*)d_in[10];
    const float* klg = (const float*)d_in[11];
    const float* klb = (const float*)d_in[12];
    float* out = (float*)d_out;

    qkv_kernel<<<dim3(DD/128, NTOK/128, 3), 256>>>(x, qw, qb, kw, kb, vw, vb);
    ln_kernel<<<(2 * BB * SS * HH) / 8, 256>>>(qlg, qlb, klg, klb);
    flash_kernel<<<dim3(SS/64, HH, BB), 256>>>();
    oproj_kernel<<<dim3(DD/128, NTOK/128), 256>>>(ow, ob, out);
}

// round 3
// speedup vs baseline: 2.5737x; 2.5737x over previous
#include <cuda_runtime.h>
#include <cuda_bf16.h>
#include <cstdint>

// Problem constants
#define BB 2
#define SS 2048
#define DD 1024
#define HH 16
#define HD 64
#define NTOK (BB*SS)   // 4096

// ---------------------------------------------------------------------------
// Scratch (__device__ globals per allocation rules). ~140 MB.
// ---------------------------------------------------------------------------
__device__ float g_q[NTOK*DD];
__device__ float g_k[NTOK*DD];
__device__ float g_v[NTOK*DD];
__device__ float g_o[NTOK*DD];
__device__ __nv_bfloat16 g_xhi[NTOK*DD];
__device__ __nv_bfloat16 g_xlo[NTOK*DD];
__device__ __nv_bfloat16 g_ohi[NTOK*DD];
__device__ __nv_bfloat16 g_olo[NTOK*DD];
__device__ __nv_bfloat16 g_vhi[NTOK*DD];
__device__ __nv_bfloat16 g_vlo[NTOK*DD];
__device__ __nv_bfloat16 g_qhi[NTOK*DD];
__device__ __nv_bfloat16 g_qlo[NTOK*DD];
__device__ __nv_bfloat16 g_khi[NTOK*DD];
__device__ __nv_bfloat16 g_klo[NTOK*DD];
__device__ __nv_bfloat16 g_whi[4][DD*DD];
__device__ __nv_bfloat16 g_wlo[4][DD*DD];

// ---------------------------------------------------------------------------
// Helpers (sm_80-era instructions only — NO tcgen05/arch-a features)
// ---------------------------------------------------------------------------
__device__ __forceinline__ uint32_t smem_u32(const void* p) {
    uint32_t a;
    asm("{ .reg .u64 t; cvta.to.shared.u64 t, %1; cvt.u32.u64 %0, t; }"
        : "=r"(a) : "l"(p));
    return a;
}
__device__ __forceinline__ void cpa16(uint32_t dst, const void* src) {
    asm volatile("cp.async.cg.shared.global [%0], [%1], 16;" :: "r"(dst), "l"(src));
}
#define CP_COMMIT() asm volatile("cp.async.commit_group;" ::: "memory")
#define CP_WAIT(n)  asm volatile("cp.async.wait_group %0;" :: "n"(n) : "memory")

__device__ __forceinline__ void ldm_x4(uint32_t* r, uint32_t addr) {
    asm volatile("ldmatrix.sync.aligned.m8n8.x4.shared.b16 {%0,%1,%2,%3}, [%4];"
                 : "=r"(r[0]), "=r"(r[1]), "=r"(r[2]), "=r"(r[3]) : "r"(addr));
}
__device__ __forceinline__ void ldm_x4_t(uint32_t* r, uint32_t addr) {
    asm volatile("ldmatrix.sync.aligned.m8n8.x4.trans.shared.b16 {%0,%1,%2,%3}, [%4];"
                 : "=r"(r[0]), "=r"(r[1]), "=r"(r[2]), "=r"(r[3]) : "r"(addr));
}
__device__ __forceinline__ void mma16816(float* d, const uint32_t* a,
                                         uint32_t b0, uint32_t b1) {
    asm volatile(
        "mma.sync.aligned.m16n8k16.row.col.f32.bf16.bf16.f32 "
        "{%0,%1,%2,%3}, {%4,%5,%6,%7}, {%8,%9}, {%0,%1,%2,%3};"
        : "+f"(d[0]), "+f"(d[1]), "+f"(d[2]), "+f"(d[3])
        : "r"(a[0]), "r"(a[1]), "r"(a[2]), "r"(a[3]), "r"(b0), "r"(b1));
}
__device__ __forceinline__ uint32_t pack_bf(float lo, float hi) {
    __nv_bfloat162 t = __floats2bfloat162_rn(lo, hi);   // x=lo half, y=hi half
    return *(uint32_t*)&t;
}
// swizzled byte offset within a tile of 128B rows (64 bf16), 16B granules
#define SW(r, g) ((r)*128 + ((((g) ^ ((r)&7))) << 4))

// ---------------------------------------------------------------------------
// fp32 -> bf16 hi/lo split. dst: 0=X, 1=O(g_o), 2..5=W[0..3], 6=V(g_v)
// ---------------------------------------------------------------------------
__global__ __launch_bounds__(256) void conv_split_kernel(const float* __restrict__ src,
                                                         int dst)
{
    __nv_bfloat16 *hi, *lo;
    const float* s = src;
    if (dst == 0)      { hi = g_xhi; lo = g_xlo; }
    else if (dst == 1) { hi = g_ohi; lo = g_olo; s = g_o; }
    else if (dst == 6) { hi = g_vhi; lo = g_vlo; s = g_v; }
    else               { hi = g_whi[dst-2]; lo = g_wlo[dst-2]; }

    int i = (blockIdx.x * 256 + threadIdx.x) * 4;
    float4 v = *(const float4*)(s + i);
    __nv_bfloat16 h0 = __float2bfloat16_rn(v.x);
    __nv_bfloat16 h1 = __float2bfloat16_rn(v.y);
    __nv_bfloat16 h2 = __float2bfloat16_rn(v.z);
    __nv_bfloat16 h3 = __float2bfloat16_rn(v.w);
    __nv_bfloat16 l0 = __float2bfloat16_rn(v.x - __bfloat162float(h0));
    __nv_bfloat16 l1 = __float2bfloat16_rn(v.y - __bfloat162float(h1));
    __nv_bfloat16 l2 = __float2bfloat16_rn(v.z - __bfloat162float(h2));
    __nv_bfloat16 l3 = __float2bfloat16_rn(v.w - __bfloat162float(h3));
    ((__nv_bfloat162*)(hi + i))[0] = __halves2bfloat162(h0, h1);
    ((__nv_bfloat162*)(hi + i))[1] = __halves2bfloat162(h2, h3);
    ((__nv_bfloat162*)(lo + i))[0] = __halves2bfloat162(l0, l1);
    ((__nv_bfloat162*)(lo + i))[1] = __halves2bfloat162(l2, l3);
}

// ---------------------------------------------------------------------------
// HMMA GEMM: Y[m,n] = sum_k A[m,k]*B[n,k] + bias[n], K virtual 3072 via
// bf16x3 split (pass 0: Ahi*Bhi, 1: Ahi*Blo, 2: Alo*Bhi).
// CTA 128x128, 8 warps (64x32 warp tile), K-chunk 64, double-buffered cp.async.
// Dynamic smem 64KB: stage s at s*32KB (A 16KB, B 16KB).
// ---------------------------------------------------------------------------
#define GEMM_SMEM (2*32768)

__device__ __forceinline__ void gemm_hmma(
    const __nv_bfloat16* __restrict__ Ahi, const __nv_bfloat16* __restrict__ Alo,
    const __nv_bfloat16* __restrict__ Bhi, const __nv_bfloat16* __restrict__ Blo,
    const float* __restrict__ bias, float* __restrict__ Y)
{
    extern __shared__ char sm[];
    const uint32_t sb = smem_u32(sm);
    const int tid = threadIdx.x;
    const int wid = tid >> 5, lane = tid & 31;
    const int warp_m = (wid >> 2) << 6;     // 0 / 64
    const int warp_n = (wid & 3) << 5;      // 0..96
    const int bm = blockIdx.y * 128, bn = blockIdx.x * 128;
    const int sub = lane >> 3, l7 = lane & 7;

    float acc[4][4][4];
#pragma unroll
    for (int mt = 0; mt < 4; mt++)
#pragma unroll
        for (int nt = 0; nt < 4; nt++)
#pragma unroll
            for (int j = 0; j < 4; j++) acc[mt][nt][j] = 0.f;

    // chunk kk (0..47): pass = kk>>4, c = kk&15, kt = c*64
    auto load_chunk = [&](int kk, int st) {
        const int p = kk >> 4, c = kk & 15;
        const __nv_bfloat16* As = (p == 2) ? Alo : Ahi;
        const __nv_bfloat16* Bs = (p == 1) ? Blo : Bhi;
        const int kt = c * 64;
        const uint32_t stA = sb + st * 32768;
        const uint32_t stB = stA + 16384;
#pragma unroll
        for (int i = 0; i < 4; i++) {
            int gid = i * 256 + tid;
            int r = gid >> 3, g = gid & 7;
            cpa16(stA + SW(r, g), As + (size_t)(bm + r) * DD + kt + g * 8);
        }
#pragma unroll
        for (int i = 0; i < 4; i++) {
            int gid = i * 256 + tid;
            int r = gid >> 3, g = gid & 7;
            cpa16(stB + SW(r, g), Bs + (size_t)(bn + r) * DD + kt + g * 8);
        }
        CP_COMMIT();
    };

    load_chunk(0, 0);

    for (int kk = 0; kk < 48; kk++) {
        const int st = kk & 1;
        if (kk < 47) { load_chunk(kk + 1, st ^ 1); CP_WAIT(1); }
        else         { CP_WAIT(0); }
        __syncthreads();

        const uint32_t stA = sb + st * 32768;
        const uint32_t stB = stA + 16384;
#pragma unroll
        for (int ks = 0; ks < 4; ks++) {
            const int g = ks * 2 + (sub >> 1);
            uint32_t a[4][4];
#pragma unroll
            for (int mt = 0; mt < 4; mt++) {
                int row = warp_m + mt * 16 + ((sub & 1) << 3) + l7;
                ldm_x4(a[mt], stA + SW(row, g));
            }
            uint32_t bf[4][2];
#pragma unroll
            for (int hb = 0; hb < 2; hb++) {
                uint32_t r4[4];
                int row = warp_n + hb * 16 + ((sub & 1) << 3) + l7;
                ldm_x4(r4, stB + SW(row, g));
                bf[hb*2][0]   = r4[0]; bf[hb*2][1]   = r4[2];
                bf[hb*2+1][0] = r4[1]; bf[hb*2+1][1] = r4[3];
            }
#pragma unroll
            for (int mt = 0; mt < 4; mt++)
#pragma unroll
                for (int nt = 0; nt < 4; nt++)
                    mma16816(acc[mt][nt], a[mt], bf[nt][0], bf[nt][1]);
        }
        __syncthreads();
    }

    // Epilogue
    const int rq = lane >> 2, cq = (lane & 3) << 1;
#pragma unroll
    for (int mt = 0; mt < 4; mt++) {
        int row = bm + warp_m + mt * 16 + rq;
#pragma unroll
        for (int nt = 0; nt < 4; nt++) {
            int col = bn + warp_n + nt * 8 + cq;
            float b0 = __ldg(bias + col), b1 = __ldg(bias + col + 1);
            float2 r0 = { acc[mt][nt][0] + b0, acc[mt][nt][1] + b1 };
            float2 r1 = { acc[mt][nt][2] + b0, acc[mt][nt][3] + b1 };
            *(float2*)(Y + (size_t)row * DD + col) = r0;
            *(float2*)(Y + (size_t)(row + 8) * DD + col) = r1;
        }
    }
}

__global__ __launch_bounds__(256) void qkv_hmma_kernel(
    const float* __restrict__ qb, const float* __restrict__ kb,
    const float* __restrict__ vb)
{
    const int z = blockIdx.z;
    const float* bias = (z == 0) ? qb : ((z == 1) ? kb : vb);
    float* Y = (z == 0) ? g_q : ((z == 1) ? g_k : g_v);
    gemm_hmma(g_xhi, g_xlo, g_whi[z], g_wlo[z], bias, Y);
}
__global__ __launch_bounds__(256) void oproj_hmma_kernel(
    const float* __restrict__ ob, float* __restrict__ out)
{
    gemm_hmma(g_ohi, g_olo, g_whi[3], g_wlo[3], ob, out);
}

// ---------------------------------------------------------------------------
// Per-head LayerNorm on Q (x0.125 softmax scale folded) and K.
// Reads fp32 g_q/g_k, writes bf16 hi/lo pairs. One warp per 64-elem row.
// ---------------------------------------------------------------------------
__global__ __launch_bounds__(256) void ln_kernel(
    const float* __restrict__ qg, const float* __restrict__ qb,
    const float* __restrict__ kg, const float* __restrict__ kb)
{
    const int warp = threadIdx.x >> 5;
    const int lane = threadIdx.x & 31;
    int row = blockIdx.x * 8 + warp;
    const int NR = BB*SS*HH;

    const float* buf; const float* g; const float* b;
    __nv_bfloat16 *hi, *lo;
    float scale;
    if (row < NR) { buf = g_q; g = qg; b = qb; hi = g_qhi; lo = g_qlo; scale = 0.125f; }
    else { buf = g_k; g = kg; b = kb; hi = g_khi; lo = g_klo; scale = 1.f; row -= NR; }

    const float* p = buf + (size_t)row * HD;
    float x0 = p[lane], x1 = p[lane + 32];

    float s = x0 + x1;
#pragma unroll
    for (int off = 16; off; off >>= 1) s += __shfl_xor_sync(~0u, s, off);
    float mu = s * (1.f / 64.f);

    float d0 = x0 - mu, d1 = x1 - mu;
    float vv = d0*d0 + d1*d1;
#pragma unroll
    for (int off = 16; off; off >>= 1) vv += __shfl_xor_sync(~0u, vv, off);
    float rstd = rsqrtf(vv * (1.f / 64.f) + 1e-5f);

    float y0 = (d0 * rstd * g[lane]      + b[lane])      * scale;
    float y1 = (d1 * rstd * g[lane + 32] + b[lane + 32]) * scale;
    __nv_bfloat16 h0 = __float2bfloat16_rn(y0);
    __nv_bfloat16 h1 = __float2bfloat16_rn(y1);
    size_t off0 = (size_t)row * HD + lane;
    hi[off0]      = h0;
    hi[off0 + 32] = h1;
    lo[off0]      = __float2bfloat16_rn(y0 - __bfloat162float(h0));
    lo[off0 + 32] = __float2bfloat16_rn(y1 - __bfloat162float(h1));
}

// ---------------------------------------------------------------------------
// Flash attention with HMMA (bf16x3 splits). 128 threads = 4 warps.
// Block = 64 queries of one (b,h); warp w owns q rows [w*16, w*16+16).
// Smem 48KB static: Qhi Qlo Khi Klo Vhi Vlo tiles [64][64] bf16, swizzled.
// ---------------------------------------------------------------------------
__global__ __launch_bounds__(128) void flash_hmma_kernel()
{
    __shared__ __align__(1024) char fsm[49152];
    const uint32_t sb = smem_u32(fsm);
    const uint32_t QH = sb, QL = sb + 8192, KH = sb + 16384, KL = sb + 24576,
                   VH = sb + 32768, VL = sb + 40960;

    const int tid = threadIdx.x;
    const int wid = tid >> 5, lane = tid & 31;
    const int sub = lane >> 3, l7 = lane & 7;
    const int rq = lane >> 2, cq = (lane & 3) << 1;
    const int b = blockIdx.z, h = blockIdx.y;
    const int q0 = blockIdx.x * 64;
    const size_t hbase = (size_t)b * SS * DD + (size_t)h * HD;

    // Load Q tiles (once)
#pragma unroll
    for (int i = 0; i < 4; i++) {
        int gid = i * 128 + tid;
        int r = gid >> 3, g = gid & 7;
        size_t src = hbase + (size_t)(q0 + r) * DD + g * 8;
        cpa16(QH + SW(r, g), g_qhi + src);
        cpa16(QL + SW(r, g), g_qlo + src);
    }
    CP_COMMIT();

    float o[8][4];
#pragma unroll
    for (int nt = 0; nt < 8; nt++)
#pragma unroll
        for (int j = 0; j < 4; j++) o[nt][j] = 0.f;
    float m0 = -1e30f, m1 = -1e30f, l0 = 0.f, l1 = 0.f;

    for (int c0 = 0; c0 < SS; c0 += 64) {
        // Load K/V hi/lo chunk tiles
        const __nv_bfloat16* srcs[4] = { g_khi, g_klo, g_vhi, g_vlo };
        const uint32_t dsts[4] = { KH, KL, VH, VL };
#pragma unroll
        for (int t = 0; t < 4; t++) {
#pragma unroll
            for (int i = 0; i < 4; i++) {
                int gid = i * 128 + tid;
                int r = gid >> 3, g = gid & 7;
                cpa16(dsts[t] + SW(r, g),
                      srcs[t] + hbase + (size_t)(c0 + r) * DD + g * 8);
            }
        }
        CP_COMMIT();
        CP_WAIT(0);
        __syncthreads();

        // ---- S = Q' @ K^T (3-pass bf16 split) ----
        float s[8][4];
#pragma unroll
        for (int nt = 0; nt < 8; nt++)
#pragma unroll
            for (int j = 0; j < 4; j++) s[nt][j] = 0.f;

#pragma unroll
        for (int pass = 0; pass < 3; pass++) {
            const uint32_t Qb = (pass < 2) ? QH : QL;
            const uint32_t Kb = (pass == 1) ? KL : KH;
#pragma unroll
            for (int ks = 0; ks < 4; ks++) {
                const int g = ks * 2 + (sub >> 1);
                uint32_t a[4];
                {
                    int row = wid * 16 + ((sub & 1) << 3) + l7;
                    ldm_x4(a, Qb + SW(row, g));
                }
#pragma unroll
                for (int nb = 0; nb < 4; nb++) {
                    uint32_t r4[4];
                    int row = nb * 16 + ((sub & 1) << 3) + l7;
                    ldm_x4(r4, Kb + SW(row, g));
                    mma16816(s[nb*2],   a, r4[0], r4[2]);
                    mma16816(s[nb*2+1], a, r4[1], r4[3]);
                }
            }
        }

        // ---- online softmax (rows rq and rq+8 of this warp's 16) ----
        float rmax0 = -1e30f, rmax1 = -1e30f;
#pragma unroll
        for (int nt = 0; nt < 8; nt++) {
            rmax0 = fmaxf(rmax0, fmaxf(s[nt][0], s[nt][1]));
            rmax1 = fmaxf(rmax1, fmaxf(s[nt][2], s[nt][3]));
        }
        rmax0 = fmaxf(rmax0, __shfl_xor_sync(~0u, rmax0, 1));
        rmax0 = fmaxf(rmax0, __shfl_xor_sync(~0u, rmax0, 2));
        rmax1 = fmaxf(rmax1, __shfl_xor_sync(~0u, rmax1, 1));
        rmax1 = fmaxf(rmax1, __shfl_xor_sync(~0u, rmax1, 2));

        float mn0 = fmaxf(m0, rmax0), mn1 = fmaxf(m1, rmax1);
        float corr0 = __expf(m0 - mn0), corr1 = __expf(m1 - mn1);
        m0 = mn0; m1 = mn1;

        float rs0 = 0.f, rs1 = 0.f;
#pragma unroll
        for (int nt = 0; nt < 8; nt++) {
            s[nt][0] = __expf(s[nt][0] - m0);
            s[nt][1] = __expf(s[nt][1] - m0);
            s[nt][2] = __expf(s[nt][2] - m1);
            s[nt][3] = __expf(s[nt][3] - m1);
            rs0 += s[nt][0] + s[nt][1];
            rs1 += s[nt][2] + s[nt][3];
        }
        rs0 += __shfl_xor_sync(~0u, rs0, 1); rs0 += __shfl_xor_sync(~0u, rs0, 2);
        rs1 += __shfl_xor_sync(~0u, rs1, 1); rs1 += __shfl_xor_sync(~0u, rs1, 2);
        l0 = l0 * corr0 + rs0;
        l1 = l1 * corr1 + rs1;
#pragma unroll
        for (int nt = 0; nt < 8; nt++) {
            o[nt][0] *= corr0; o[nt][1] *= corr0;
            o[nt][2] *= corr1; o[nt][3] *= corr1;
        }

        // ---- P -> A-fragments (hi/lo), in-register ----
        uint32_t phi[4][4], plo[4][4];
#pragma unroll
        for (int kvt = 0; kvt < 4; kvt++) {
            const float* t0 = s[kvt*2];
            const float* t1 = s[kvt*2+1];
            phi[kvt][0] = pack_bf(t0[0], t0[1]);
            phi[kvt][1] = pack_bf(t0[2], t0[3]);
            phi[kvt][2] = pack_bf(t1[0], t1[1]);
            phi[kvt][3] = pack_bf(t1[2], t1[3]);
            __nv_bfloat162 h0 = *(__nv_bfloat162*)&phi[kvt][0];
            __nv_bfloat162 h1 = *(__nv_bfloat162*)&phi[kvt][1];
            __nv_bfloat162 h2 = *(__nv_bfloat162*)&phi[kvt][2];
            __nv_bfloat162 h3 = *(__nv_bfloat162*)&phi[kvt][3];
            plo[kvt][0] = pack_bf(t0[0] - __bfloat162float(h0.x),
                                  t0[1] - __bfloat162float(h0.y));
            plo[kvt][1] = pack_bf(t0[2] - __bfloat162float(h1.x),
                                  t0[3] - __bfloat162float(h1.y));
            plo[kvt][2] = pack_bf(t1[0] - __bfloat162float(h2.x),
                                  t1[1] - __bfloat162float(h2.y));
            plo[kvt][3] = pack_bf(t1[2] - __bfloat162float(h3.x),
                                  t1[3] - __bfloat162float(h3.y));
        }

        // ---- O += P @ V (3-pass) ----
#pragma unroll
        for (int pass = 0; pass < 3; pass++) {
            const uint32_t (*Pa)[4] = (pass < 2) ? phi : plo;
            const uint32_t Vb = (pass == 1) ? VL : VH;
#pragma unroll
            for (int kvt = 0; kvt < 4; kvt++) {
#pragma unroll
                for (int db = 0; db < 4; db++) {
                    uint32_t r4[4];
                    int row = kvt * 16 + ((sub & 1) << 3) + l7;
                    int g = db * 2 + (sub >> 1);
                    ldm_x4_t(r4, Vb + SW(row, g));
                    mma16816(o[db*2],   Pa[kvt], r4[0], r4[1]);
                    mma16816(o[db*2+1], Pa[kvt], r4[2], r4[3]);
                }
            }
        }
        __syncthreads();   // done reading K/V before next chunk overwrites
    }

    // ---- finalize: divide by l, write fp32 g_o ----
    float inv0 = 1.f / l0, inv1 = 1.f / l1;
    int row0 = q0 + wid * 16 + rq;
#pragma unroll
    for (int nt = 0; nt < 8; nt++) {
        int col = nt * 8 + cq;
        float2 w0 = { o[nt][0] * inv0, o[nt][1] * inv0 };
        float2 w1 = { o[nt][2] * inv1, o[nt][3] * inv1 };
        *(float2*)(g_o + hbase + (size_t)row0 * DD + col) = w0;
        *(float2*)(g_o + hbase + (size_t)(row0 + 8) * DD + col) = w1;
    }
}

// ---------------------------------------------------------------------------
extern "C" void kernel_launch(void* const* d_in, const int* in_sizes, int n_in,
                              void* d_out, int out_size)
{
    const float* x   = (const float*)d_in[0];
    const float* qw  = (const float*)d_in[1];
    const float* qb  = (const float*)d_in[2];
    const float* kw  = (const float*)d_in[3];
    const float* kb  = (const float*)d_in[4];
    const float* vw  = (const float*)d_in[5];
    const float* vb  = (const float*)d_in[6];
    const float* ow  = (const float*)d_in[7];
    const float* ob  = (const float*)d_in[8];
    const float* qlg = (const float*)d_in[9];
    const float* qlb = (const float*)d_in[10];
    const float* klg = (const float*)d_in[11];
    const float* klb = (const float*)d_in[12];
    float* out = (float*)d_out;

    static bool attr_done = false;
    if (!attr_done) {
        cudaFuncSetAttribute(qkv_hmma_kernel,
                             cudaFuncAttributeMaxDynamicSharedMemorySize, GEMM_SMEM);
        cudaFuncSetAttribute(oproj_hmma_kernel,
                             cudaFuncAttributeMaxDynamicSharedMemorySize, GEMM_SMEM);
        attr_done = true;
    }

    // fp32 -> bf16 hi/lo splits (X + 4 weights)
    conv_split_kernel<<<NTOK*DD/1024, 256>>>(x,  0);
    conv_split_kernel<<<DD*DD/1024,  256>>>(qw, 2);
    conv_split_kernel<<<DD*DD/1024,  256>>>(kw, 3);
    conv_split_kernel<<<DD*DD/1024,  256>>>(vw, 4);
    conv_split_kernel<<<DD*DD/1024,  256>>>(ow, 5);

    qkv_hmma_kernel<<<dim3(DD/128, NTOK/128, 3), 256, GEMM_SMEM>>>(qb, kb, vb);
    ln_kernel<<<(2 * BB * SS * HH) / 8, 256>>>(qlg, qlb, klg, klb);
    conv_split_kernel<<<NTOK*DD/1024, 256>>>(x, 6);   // g_v -> vhi/vlo
    flash_hmma_kernel<<<dim3(SS/64, HH, BB), 128>>>();
    conv_split_kernel<<<NTOK*DD/1024, 256>>>(x, 1);   // g_o -> ohi/olo
    oproj_hmma_kernel<<<dim3(DD/128, NTOK/128), 256, GEMM_SMEM>>>(ob, out);
}